// round 2
// baseline (speedup 1.0000x reference)
#include <cuda_runtime.h>
#include <math.h>

#define BATCH   2
#define SEQL    2048
#define EMBED   1024
#define HEADS   16
#define HDIM    64
#define M_TOTAL (BATCH*SEQL)   /* 4096 */
#define QKV_N   (3*EMBED)      /* 3072 */

// Scratch (alloc-free rule: __device__ globals)
__device__ float g_qkv [M_TOTAL * (size_t)QKV_N];   // [b,s,3,h,d] flattened = [4096][3072]
__device__ float g_attn[M_TOTAL * (size_t)EMBED];   // attention output [4096][1024]

// ---------------------------------------------------------------------------
// C[M,N] = A[M,K] @ B[N,K]^T (+ bias).  128x128 tile, 8x8 per thread, BK=8.
// ---------------------------------------------------------------------------
template<bool HAS_BIAS>
__global__ __launch_bounds__(256)
void sgemm_nt(const float* __restrict__ A, const float* __restrict__ B,
              float* __restrict__ C, int M, int N, int K,
              const float* __restrict__ bias)
{
    __shared__ float As[8][128];
    __shared__ float Bs[8][128];

    const int tid = threadIdx.x;
    const int bm  = blockIdx.y * 128;
    const int bn  = blockIdx.x * 128;
    const int tx  = tid & 15;
    const int ty  = tid >> 4;

    const int lr = tid >> 1;          // 0..127: row within tile
    const int lc = (tid & 1) * 4;     // 0 or 4: k offset

    float acc[8][8];
#pragma unroll
    for (int i = 0; i < 8; i++)
#pragma unroll
        for (int j = 0; j < 8; j++) acc[i][j] = 0.f;

    const float* Aptr = A + (size_t)(bm + lr) * K + lc;
    const float* Bptr = B + (size_t)(bn + lr) * K + lc;

    for (int kt = 0; kt < K; kt += 8) {
        float4 av = *(const float4*)(Aptr + kt);
        float4 bv = *(const float4*)(Bptr + kt);
        As[lc+0][lr] = av.x; As[lc+1][lr] = av.y; As[lc+2][lr] = av.z; As[lc+3][lr] = av.w;
        Bs[lc+0][lr] = bv.x; Bs[lc+1][lr] = bv.y; Bs[lc+2][lr] = bv.z; Bs[lc+3][lr] = bv.w;
        __syncthreads();
#pragma unroll
        for (int k = 0; k < 8; k++) {
            float a[8], b[8];
#pragma unroll
            for (int i = 0; i < 8; i++) a[i] = As[k][ty*8 + i];
#pragma unroll
            for (int j = 0; j < 8; j++) b[j] = Bs[k][tx*8 + j];
#pragma unroll
            for (int i = 0; i < 8; i++)
#pragma unroll
                for (int j = 0; j < 8; j++)
                    acc[i][j] += a[i] * b[j];
        }
        __syncthreads();
    }

#pragma unroll
    for (int i = 0; i < 8; i++) {
        const int row = bm + ty*8 + i;
        float* crow = C + (size_t)row * N + bn + tx*8;
#pragma unroll
        for (int j = 0; j < 8; j++) {
            float v = acc[i][j];
            if (HAS_BIAS) v += bias[bn + tx*8 + j];
            crow[j] = v;
        }
    }
}

// ---------------------------------------------------------------------------
// Flash attention: one block = 64 query rows of one (batch, head).
// Online softmax over 2048 keys in tiles of 32.
// ---------------------------------------------------------------------------
#define BM 64
#define BN 32

__global__ __launch_bounds__(256)
void attn_kernel(const float* __restrict__ qkv, const int* __restrict__ mask,
                 float* __restrict__ out)
{
    // Q stored transposed: Qs[d][r]
    __shared__ float Qs[HDIM][BM + 4];          // 64 x 68
    // K/V shared buffer: K transposed as Kt[d][c] stride 34; V natural [n][d] stride 68
    __shared__ float KV[BN * 68];               // 2176 floats (>= 64*34)
    __shared__ float Ps[BM][BN + 1];            // 64 x 33
    __shared__ float m_s[BM], l_s[BM], alpha_s[BM];
    __shared__ float maskv[BN];                 // additive: 0 or -inf

    const int bh  = blockIdx.y;
    const int b   = bh / HEADS;
    const int h   = bh % HEADS;
    const int q0  = blockIdx.x * BM;
    const int tid = threadIdx.x;
    const int tx  = tid & 15;
    const int ty  = tid >> 4;

    const float scale = 0.125f;  // 1/sqrt(64)

    // Load Q tile, store transposed Qs[d][r]
    for (int idx = tid; idx < BM * 16; idx += 256) {
        const int r  = idx >> 4;
        const int c4 = (idx & 15) * 4;
        const float* src = qkv + ((size_t)(b*SEQL + q0 + r) * 3 + 0) * EMBED + h*HDIM + c4;
        float4 v = *(const float4*)src;
        Qs[c4+0][r] = v.x; Qs[c4+1][r] = v.y; Qs[c4+2][r] = v.z; Qs[c4+3][r] = v.w;
    }
    if (tid < BM) { m_s[tid] = -INFINITY; l_s[tid] = 0.f; }

    float O[4][4];
#pragma unroll
    for (int i = 0; i < 4; i++)
#pragma unroll
        for (int j = 0; j < 4; j++) O[i][j] = 0.f;

    for (int kt = 0; kt < SEQL; kt += BN) {
        __syncthreads();  // previous iteration's V reads done before K overwrite

        // Load K tile transposed: Kt[d][c] with row stride 34
        for (int idx = tid; idx < BN * 16; idx += 256) {
            const int r  = idx >> 4;        // key within tile
            const int c4 = (idx & 15) * 4;  // d offset
            const float* src = qkv + ((size_t)(b*SEQL + kt + r) * 3 + 1) * EMBED + h*HDIM + c4;
            float4 v = *(const float4*)src;
            KV[(c4+0)*34 + r] = v.x;
            KV[(c4+1)*34 + r] = v.y;
            KV[(c4+2)*34 + r] = v.z;
            KV[(c4+3)*34 + r] = v.w;
        }
        if (tid < BN)
            maskv[tid] = (mask[b*SEQL + kt + tid] == 0) ? -INFINITY : 0.f;
        __syncthreads();

        // S[4 rows][2 cols] per thread: rows 4*ty+i, cols 2*tx+j
        float s[4][2];
#pragma unroll
        for (int i = 0; i < 4; i++) { s[i][0] = 0.f; s[i][1] = 0.f; }
#pragma unroll 8
        for (int d = 0; d < HDIM; d++) {
            float4 a = *(const float4*)&Qs[d][4*ty];
            float2 kk = *(const float2*)&KV[d*34 + 2*tx];
            s[0][0] += a.x * kk.x;  s[0][1] += a.x * kk.y;
            s[1][0] += a.y * kk.x;  s[1][1] += a.y * kk.y;
            s[2][0] += a.z * kk.x;  s[2][1] += a.z * kk.y;
            s[3][0] += a.w * kk.x;  s[3][1] += a.w * kk.y;
        }
#pragma unroll
        for (int i = 0; i < 4; i++) {
#pragma unroll
            for (int j = 0; j < 2; j++)
                Ps[4*ty + i][2*tx + j] = s[i][j] * scale + maskv[2*tx + j];
        }
        __syncthreads();  // K reads done; Ps raw scores visible

        // Load V tile (natural layout [n][d], row stride 68, aligned float4)
        for (int idx = tid; idx < BN * 16; idx += 256) {
            const int r  = idx >> 4;
            const int c4 = (idx & 15) * 4;
            const float* src = qkv + ((size_t)(b*SEQL + kt + r) * 3 + 2) * EMBED + h*HDIM + c4;
            float4 v = *(const float4*)src;
            *(float4*)&KV[r*68 + c4] = v;
        }

        // Online softmax: one thread per query row
        if (tid < BM) {
            const float mold = m_s[tid];
            float mx = mold;
#pragma unroll 8
            for (int n = 0; n < BN; n++) mx = fmaxf(mx, Ps[tid][n]);
            const float mx2 = (mx == -INFINITY) ? 0.f : mx;  // NaN guard (fully masked)
            const float alpha = __expf(mold - mx2);
            float sum = 0.f;
#pragma unroll 8
            for (int n = 0; n < BN; n++) {
                const float p = __expf(Ps[tid][n] - mx2);
                Ps[tid][n] = p;
                sum += p;
            }
            l_s[tid]     = alpha * l_s[tid] + sum;
            m_s[tid]     = mx;
            alpha_s[tid] = alpha;
        }
        __syncthreads();  // V + P + alpha ready

        // Rescale O and accumulate P @ V. Thread owns rows 4*ty+i, cols 4*tx+j.
        float al[4];
#pragma unroll
        for (int i = 0; i < 4; i++) al[i] = alpha_s[4*ty + i];
#pragma unroll
        for (int i = 0; i < 4; i++)
#pragma unroll
            for (int j = 0; j < 4; j++) O[i][j] *= al[i];

#pragma unroll 4
        for (int n = 0; n < BN; n++) {
            float p[4];
#pragma unroll
            for (int i = 0; i < 4; i++) p[i] = Ps[4*ty + i][n];
            float4 vv = *(const float4*)&KV[n*68 + 4*tx];
            O[0][0] += p[0]*vv.x; O[0][1] += p[0]*vv.y; O[0][2] += p[0]*vv.z; O[0][3] += p[0]*vv.w;
            O[1][0] += p[1]*vv.x; O[1][1] += p[1]*vv.y; O[1][2] += p[1]*vv.z; O[1][3] += p[1]*vv.w;
            O[2][0] += p[2]*vv.x; O[2][1] += p[2]*vv.y; O[2][2] += p[2]*vv.z; O[2][3] += p[2]*vv.w;
            O[3][0] += p[3]*vv.x; O[3][1] += p[3]*vv.y; O[3][2] += p[3]*vv.z; O[3][3] += p[3]*vv.w;
        }
    }

    // Final normalize + write: out[b][q0+r][h*64 + 4*tx + j]
#pragma unroll
    for (int i = 0; i < 4; i++) {
        const int r = 4*ty + i;
        const float inv = 1.f / l_s[r];
        float* dst = out + (size_t)(b*SEQL + q0 + r) * EMBED + h*HDIM + 4*tx;
        float4 o;
        o.x = O[i][0]*inv; o.y = O[i][1]*inv; o.z = O[i][2]*inv; o.w = O[i][3]*inv;
        *(float4*)dst = o;
    }
}

// ---------------------------------------------------------------------------
extern "C" void kernel_launch(void* const* d_in, const int* in_sizes, int n_in,
                              void* d_out, int out_size)
{
    const float* x     = (const float*)d_in[0];
    const int*   mask  = (const int*)  d_in[1];
    const float* qkv_w = (const float*)d_in[2];
    const float* out_w = (const float*)d_in[3];
    const float* out_b = (const float*)d_in[4];
    float* out = (float*)d_out;

    float* qkv;  cudaGetSymbolAddress((void**)&qkv,  g_qkv);
    float* attn; cudaGetSymbolAddress((void**)&attn, g_attn);

    // 1) QKV projection: [4096,3072] = x[4096,1024] @ qkv_w[3072,1024]^T
    sgemm_nt<false><<<dim3(QKV_N/128, M_TOTAL/128), 256>>>(
        x, qkv_w, qkv, M_TOTAL, QKV_N, EMBED, nullptr);

    // 2) Attention
    attn_kernel<<<dim3(SEQL/BM, BATCH*HEADS), 256>>>(qkv, mask, attn);

    // 3) Output projection: [4096,1024] = attn @ out_w^T + out_b
    sgemm_nt<true><<<dim3(EMBED/128, M_TOTAL/128), 256>>>(
        attn, out_w, out, M_TOTAL, EMBED, EMBED, out_b);
}

// round 5
// speedup vs baseline: 3.4162x; 3.4162x over previous
#include <cuda_runtime.h>
#include <math.h>
#include <stdint.h>

#define BATCH   2
#define SEQL    2048
#define EMBED   1024
#define HEADS   16
#define HDIM    64
#define M_TOTAL (BATCH*SEQL)   /* 4096 */
#define QKV_N   (3*EMBED)      /* 3072 */

// Scratch (alloc-free rule: __device__ globals)
__device__ float g_qkv [M_TOTAL * (size_t)QKV_N];   // [b,s][3*1024] ; col = sel*1024 + h*64 + d
__device__ float g_attn[M_TOTAL * (size_t)EMBED];   // attention output [4096][1024]

// ---------------------------------------------------------------------------
// helpers
// ---------------------------------------------------------------------------
__device__ __forceinline__ float tf32r(float x) {
    uint32_t u; asm("cvt.rna.tf32.f32 %0, %1;" : "=r"(u) : "f"(x));
    return __uint_as_float(u);
}
__device__ __forceinline__ uint32_t fb(float x) { return __float_as_uint(x); }

// D(16x8) += A(16x8) * B(8x8),  A row-major frag, B col-major frag, tf32
__device__ __forceinline__ void mma_tf32(float c[4],
    uint32_t a0, uint32_t a1, uint32_t a2, uint32_t a3,
    uint32_t b0, uint32_t b1)
{
    asm volatile(
        "mma.sync.aligned.m16n8k8.row.col.f32.tf32.tf32.f32 "
        "{%0,%1,%2,%3}, {%4,%5,%6,%7}, {%8,%9}, {%0,%1,%2,%3};"
        : "+f"(c[0]), "+f"(c[1]), "+f"(c[2]), "+f"(c[3])
        : "r"(a0), "r"(a1), "r"(a2), "r"(a3), "r"(b0), "r"(b1));
}

// ---------------------------------------------------------------------------
// C[M,N] = A[M,K] @ B[N,K]^T (+bias), tf32 tensor cores.
// 128x128 block tile, BK=32, 8 warps (2x4), warp tile 64x32.
// ---------------------------------------------------------------------------
template<bool HAS_BIAS>
__global__ __launch_bounds__(256)
void gemm_tf32(const float* __restrict__ A, const float* __restrict__ B,
               float* __restrict__ C, int M, int N, int K,
               const float* __restrict__ bias)
{
    __shared__ float As[128][36];   // [m][k], stride 36 -> conflict-free frags
    __shared__ float Bs[128][36];   // [n][k]

    const int tid  = threadIdx.x;
    const int lane = tid & 31, wid = tid >> 5;
    const int g = lane >> 2, t = lane & 3;
    const int wr = wid >> 2, wc = wid & 3;           // 2 x 4 warp grid
    const int bm = blockIdx.y * 128, bn = blockIdx.x * 128;

    const int lrow = tid >> 3;                       // 0..31
    const int lcol = (tid & 7) << 2;                 // 0,4,...,28

    const float* Ap = A + (size_t)(bm + lrow) * K + lcol;
    const float* Bp = B + (size_t)(bn + lrow) * K + lcol;
    const size_t rstep = (size_t)32 * K;

    float4 ra[4], rb[4];
#pragma unroll
    for (int i = 0; i < 4; i++) {
        ra[i] = *(const float4*)(Ap + i * rstep);
        rb[i] = *(const float4*)(Bp + i * rstep);
    }

    float acc[4][4][4];
#pragma unroll
    for (int mf = 0; mf < 4; mf++)
#pragma unroll
        for (int nf = 0; nf < 4; nf++)
#pragma unroll
            for (int i = 0; i < 4; i++) acc[mf][nf][i] = 0.f;

    for (int kt = 0; kt < K; kt += 32) {
#pragma unroll
        for (int i = 0; i < 4; i++) {
            float* ad = &As[lrow + i*32][lcol];
            ad[0]=tf32r(ra[i].x); ad[1]=tf32r(ra[i].y); ad[2]=tf32r(ra[i].z); ad[3]=tf32r(ra[i].w);
            float* bd = &Bs[lrow + i*32][lcol];
            bd[0]=tf32r(rb[i].x); bd[1]=tf32r(rb[i].y); bd[2]=tf32r(rb[i].z); bd[3]=tf32r(rb[i].w);
        }
        __syncthreads();
        if (kt + 32 < K) {
#pragma unroll
            for (int i = 0; i < 4; i++) {
                ra[i] = *(const float4*)(Ap + (kt + 32) + i * rstep);
                rb[i] = *(const float4*)(Bp + (kt + 32) + i * rstep);
            }
        }
#pragma unroll
        for (int ks = 0; ks < 4; ks++) {
            const int k0 = ks * 8;
            uint32_t af[4][4], bf[4][2];
#pragma unroll
            for (int mf = 0; mf < 4; mf++) {
                const int r = wr*64 + mf*16;
                af[mf][0] = fb(As[r + g    ][k0 + t    ]);
                af[mf][1] = fb(As[r + g + 8][k0 + t    ]);
                af[mf][2] = fb(As[r + g    ][k0 + t + 4]);
                af[mf][3] = fb(As[r + g + 8][k0 + t + 4]);
            }
#pragma unroll
            for (int nf = 0; nf < 4; nf++) {
                const int c = wc*32 + nf*8;
                bf[nf][0] = fb(Bs[c + g][k0 + t    ]);
                bf[nf][1] = fb(Bs[c + g][k0 + t + 4]);
            }
#pragma unroll
            for (int mf = 0; mf < 4; mf++)
#pragma unroll
                for (int nf = 0; nf < 4; nf++)
                    mma_tf32(acc[mf][nf], af[mf][0], af[mf][1], af[mf][2], af[mf][3],
                             bf[nf][0], bf[nf][1]);
        }
        __syncthreads();
    }

#pragma unroll
    for (int mf = 0; mf < 4; mf++) {
        const int r = bm + wr*64 + mf*16 + g;
#pragma unroll
        for (int nf = 0; nf < 4; nf++) {
            const int c = bn + wc*32 + nf*8 + 2*t;
            float b0 = HAS_BIAS ? bias[c]     : 0.f;
            float b1 = HAS_BIAS ? bias[c + 1] : 0.f;
            *(float2*)&C[(size_t)r       * N + c] = make_float2(acc[mf][nf][0] + b0, acc[mf][nf][1] + b1);
            *(float2*)&C[(size_t)(r + 8) * N + c] = make_float2(acc[mf][nf][2] + b0, acc[mf][nf][3] + b1);
        }
    }
}

// ---------------------------------------------------------------------------
// Flash attention with tf32 tensor cores.
// Block: 4 warps, BM=64 queries, BN=64 keys/tile. Warp owns 16 query rows.
// Q frags persistent in regs; online softmax in regs; P via smem for PV mma.
// ---------------------------------------------------------------------------
#define QS_STRIDE 68   // Qs/Ks/Ps [row][d or key] padded
#define VS_STRIDE 72   // Vs natural [key][d]; stride%32==8 -> conflict-free B frags
#define SMEM_FLOATS (3*64*QS_STRIDE + 64*VS_STRIDE + 64)

__global__ __launch_bounds__(128)
void attn_tf32(const float* __restrict__ qkv, const int* __restrict__ mask,
               float* __restrict__ out)
{
    extern __shared__ float sm[];
    float* Qs = sm;                         // [64][68]
    float* Ks = sm + 64*QS_STRIDE;          // [64][68]  (key, d)
    float* Ps = sm + 2*64*QS_STRIDE;        // [64][68]  (qrow, key)
    float* Vs = sm + 3*64*QS_STRIDE;        // [64][72]  (key, d)
    float* maskadd = Vs + 64*VS_STRIDE;     // [64]

    const int bhead = blockIdx.y;
    const int b = bhead >> 4, h = bhead & 15;
    const int q0 = blockIdx.x * 64;
    const int tid = threadIdx.x;
    const int lane = tid & 31, wid = tid >> 5;
    const int g = lane >> 2, t = lane & 3;
    const int r0 = wid * 16;                // warp's query-row offset in tile

    // ---- load Q tile (tf32-rounded), build persistent A frags ----
    for (int i = tid; i < 64*16; i += 128) {
        const int r = i >> 4, c4 = (i & 15) << 2;
        const float* src = qkv + (size_t)(b*SEQL + q0 + r)*QKV_N + h*HDIM + c4;
        float4 v = *(const float4*)src;
        float* d = Qs + r*QS_STRIDE + c4;
        d[0]=tf32r(v.x); d[1]=tf32r(v.y); d[2]=tf32r(v.z); d[3]=tf32r(v.w);
    }
    __syncthreads();
    uint32_t qa[8][4];
#pragma unroll
    for (int ks = 0; ks < 8; ks++) {
        const int k0 = ks * 8;
        qa[ks][0] = fb(Qs[(r0 + g    )*QS_STRIDE + k0 + t    ]);
        qa[ks][1] = fb(Qs[(r0 + g + 8)*QS_STRIDE + k0 + t    ]);
        qa[ks][2] = fb(Qs[(r0 + g    )*QS_STRIDE + k0 + t + 4]);
        qa[ks][3] = fb(Qs[(r0 + g + 8)*QS_STRIDE + k0 + t + 4]);
    }

    float oc[8][4];
#pragma unroll
    for (int nf = 0; nf < 8; nf++)
#pragma unroll
        for (int i = 0; i < 4; i++) oc[nf][i] = 0.f;
    float m0 = -INFINITY, m1 = -INFINITY, l0 = 0.f, l1 = 0.f;

    for (int kt = 0; kt < SEQL; kt += 64) {
        __syncthreads();   // prior tile's K/V reads done
        // ---- load K and V tiles (tf32-rounded) ----
        for (int i = tid; i < 64*16; i += 128) {
            const int r = i >> 4, c4 = (i & 15) << 2;
            const size_t rowbase = (size_t)(b*SEQL + kt + r)*QKV_N + h*HDIM + c4;
            float4 kv = *(const float4*)(qkv + rowbase + EMBED);
            float* kd = Ks + r*QS_STRIDE + c4;
            kd[0]=tf32r(kv.x); kd[1]=tf32r(kv.y); kd[2]=tf32r(kv.z); kd[3]=tf32r(kv.w);
            float4 vv = *(const float4*)(qkv + rowbase + 2*EMBED);
            float* vd = Vs + r*VS_STRIDE + c4;
            vd[0]=tf32r(vv.x); vd[1]=tf32r(vv.y); vd[2]=tf32r(vv.z); vd[3]=tf32r(vv.w);
        }
        if (tid < 64)
            maskadd[tid] = (mask[b*SEQL + kt + tid] == 0) ? -INFINITY : 0.f;
        __syncthreads();

        // ---- S = Q K^T  (16 x 64 per warp) ----
        float sc[8][4];
#pragma unroll
        for (int nf = 0; nf < 8; nf++)
#pragma unroll
            for (int i = 0; i < 4; i++) sc[nf][i] = 0.f;
#pragma unroll
        for (int ks = 0; ks < 8; ks++) {
            const int k0 = ks * 8;
#pragma unroll
            for (int nf = 0; nf < 8; nf++) {
                uint32_t kb0 = fb(Ks[(nf*8 + g)*QS_STRIDE + k0 + t    ]);
                uint32_t kb1 = fb(Ks[(nf*8 + g)*QS_STRIDE + k0 + t + 4]);
                mma_tf32(sc[nf], qa[ks][0], qa[ks][1], qa[ks][2], qa[ks][3], kb0, kb1);
            }
        }

        // ---- scale + mask + online softmax (rows g and g+8, in regs) ----
        float mx0 = -INFINITY, mx1 = -INFINITY;
#pragma unroll
        for (int nf = 0; nf < 8; nf++) {
            const float ma = maskadd[nf*8 + 2*t];
            const float mb = maskadd[nf*8 + 2*t + 1];
            sc[nf][0] = sc[nf][0]*0.125f + ma;
            sc[nf][1] = sc[nf][1]*0.125f + mb;
            sc[nf][2] = sc[nf][2]*0.125f + ma;
            sc[nf][3] = sc[nf][3]*0.125f + mb;
            mx0 = fmaxf(mx0, fmaxf(sc[nf][0], sc[nf][1]));
            mx1 = fmaxf(mx1, fmaxf(sc[nf][2], sc[nf][3]));
        }
        mx0 = fmaxf(mx0, __shfl_xor_sync(0xffffffffu, mx0, 1));
        mx0 = fmaxf(mx0, __shfl_xor_sync(0xffffffffu, mx0, 2));
        mx1 = fmaxf(mx1, __shfl_xor_sync(0xffffffffu, mx1, 1));
        mx1 = fmaxf(mx1, __shfl_xor_sync(0xffffffffu, mx1, 2));

        const float nm0 = fmaxf(m0, mx0), nm1 = fmaxf(m1, mx1);
        const float gd0 = (nm0 == -INFINITY) ? 0.f : nm0;   // fully-masked guard
        const float gd1 = (nm1 == -INFINITY) ? 0.f : nm1;
        const float alpha0 = __expf(m0 - gd0);
        const float alpha1 = __expf(m1 - gd1);

        float rs0 = 0.f, rs1 = 0.f;
#pragma unroll
        for (int nf = 0; nf < 8; nf++) {
            const float p0 = __expf(sc[nf][0] - gd0);
            const float p1 = __expf(sc[nf][1] - gd0);
            const float p2 = __expf(sc[nf][2] - gd1);
            const float p3 = __expf(sc[nf][3] - gd1);
            rs0 += p0 + p1; rs1 += p2 + p3;
            *(float2*)&Ps[(r0 + g    )*QS_STRIDE + nf*8 + 2*t] = make_float2(tf32r(p0), tf32r(p1));
            *(float2*)&Ps[(r0 + g + 8)*QS_STRIDE + nf*8 + 2*t] = make_float2(tf32r(p2), tf32r(p3));
        }
        rs0 += __shfl_xor_sync(0xffffffffu, rs0, 1);
        rs0 += __shfl_xor_sync(0xffffffffu, rs0, 2);
        rs1 += __shfl_xor_sync(0xffffffffu, rs1, 1);
        rs1 += __shfl_xor_sync(0xffffffffu, rs1, 2);

        l0 = l0*alpha0 + rs0;  l1 = l1*alpha1 + rs1;
        m0 = nm0;  m1 = nm1;
#pragma unroll
        for (int nf = 0; nf < 8; nf++) {
            oc[nf][0] *= alpha0; oc[nf][1] *= alpha0;
            oc[nf][2] *= alpha1; oc[nf][3] *= alpha1;
        }
        __syncwarp();   // Ps visible within warp (each warp owns its 16 rows)

        // ---- O += P V  (P as A frags from smem; V natural layout as B col frags) ----
#pragma unroll
        for (int ks = 0; ks < 8; ks++) {
            const int k0 = ks * 8;
            const uint32_t pa0 = fb(Ps[(r0 + g    )*QS_STRIDE + k0 + t    ]);
            const uint32_t pa1 = fb(Ps[(r0 + g + 8)*QS_STRIDE + k0 + t    ]);
            const uint32_t pa2 = fb(Ps[(r0 + g    )*QS_STRIDE + k0 + t + 4]);
            const uint32_t pa3 = fb(Ps[(r0 + g + 8)*QS_STRIDE + k0 + t + 4]);
#pragma unroll
            for (int nf = 0; nf < 8; nf++) {
                // B[k=key][n=dim] = Vs natural
                uint32_t vb0 = fb(Vs[(k0 + t    )*VS_STRIDE + nf*8 + g]);
                uint32_t vb1 = fb(Vs[(k0 + t + 4)*VS_STRIDE + nf*8 + g]);
                mma_tf32(oc[nf], pa0, pa1, pa2, pa3, vb0, vb1);
            }
        }
    }

    // ---- normalize + write ----
    const float inv0 = 1.f / l0, inv1 = 1.f / l1;
    const int row = b*SEQL + q0 + r0 + g;
#pragma unroll
    for (int nf = 0; nf < 8; nf++) {
        const int c = h*HDIM + nf*8 + 2*t;
        *(float2*)&out[(size_t)row       * EMBED + c] = make_float2(oc[nf][0]*inv0, oc[nf][1]*inv0);
        *(float2*)&out[(size_t)(row + 8) * EMBED + c] = make_float2(oc[nf][2]*inv1, oc[nf][3]*inv1);
    }
}

// ---------------------------------------------------------------------------
extern "C" void kernel_launch(void* const* d_in, const int* in_sizes, int n_in,
                              void* d_out, int out_size)
{
    const float* x     = (const float*)d_in[0];
    const int*   mask  = (const int*)  d_in[1];
    const float* qkv_w = (const float*)d_in[2];
    const float* out_w = (const float*)d_in[3];
    const float* out_b = (const float*)d_in[4];
    float* out = (float*)d_out;

    float* qkv;  cudaGetSymbolAddress((void**)&qkv,  g_qkv);
    float* attn; cudaGetSymbolAddress((void**)&attn, g_attn);

    const int attn_smem = SMEM_FLOATS * (int)sizeof(float);
    cudaFuncSetAttribute(attn_tf32, cudaFuncAttributeMaxDynamicSharedMemorySize, attn_smem);

    // 1) QKV projection: [4096,3072] = x @ qkv_w^T
    gemm_tf32<false><<<dim3(QKV_N/128, M_TOTAL/128), 256>>>(
        x, qkv_w, qkv, M_TOTAL, QKV_N, EMBED, nullptr);

    // 2) Attention
    attn_tf32<<<dim3(SEQL/64, BATCH*HEADS), 128, attn_smem>>>(qkv, mask, attn);

    // 3) Output projection: [4096,1024] = attn @ out_w^T + out_b
    gemm_tf32<true><<<dim3(EMBED/128, M_TOTAL/128), 256>>>(
        attn, out_w, out, M_TOTAL, EMBED, EMBED, out_b);
}

// round 9
// speedup vs baseline: 3.7638x; 1.1018x over previous
#include <cuda_runtime.h>
#include <math.h>
#include <stdint.h>

#define BATCH   2
#define SEQL    2048
#define EMBED   1024
#define HEADS   16
#define HDIM    64
#define M_TOTAL (BATCH*SEQL)   /* 4096 */
#define QKV_N   (3*EMBED)      /* 3072 */

// Scratch (alloc-free rule: __device__ globals)
__device__ float g_qkv [M_TOTAL * (size_t)QKV_N];
__device__ float g_attn[M_TOTAL * (size_t)EMBED];

// ---------------------------------------------------------------------------
__device__ __forceinline__ float tf32r(float x) {
    uint32_t u; asm("cvt.rna.tf32.f32 %0, %1;" : "=r"(u) : "f"(x));
    return __uint_as_float(u);
}
__device__ __forceinline__ uint32_t fb(float x) { return __float_as_uint(x); }

__device__ __forceinline__ void mma_tf32(float c[4],
    uint32_t a0, uint32_t a1, uint32_t a2, uint32_t a3,
    uint32_t b0, uint32_t b1)
{
    asm volatile(
        "mma.sync.aligned.m16n8k8.row.col.f32.tf32.tf32.f32 "
        "{%0,%1,%2,%3}, {%4,%5,%6,%7}, {%8,%9}, {%0,%1,%2,%3};"
        : "+f"(c[0]), "+f"(c[1]), "+f"(c[2]), "+f"(c[3])
        : "r"(a0), "r"(a1), "r"(a2), "r"(a3), "r"(b0), "r"(b1));
}

// ---------------------------------------------------------------------------
// C[M,N] = A[M,K] @ B[N,K]^T (+bias), tf32 tensor cores.
// 128x128 block tile, BK=32, 8 warps (2x4), warp tile 64x32.
// Double-buffered smem: ONE __syncthreads per K-slab.
// ---------------------------------------------------------------------------
#define GSLAB 4608                 /* 128*36 floats per buffer half */
#define GEMM_SMEM_BYTES (4*GSLAB*4) /* As[2]+Bs[2] = 73728 B */

template<bool HAS_BIAS>
__global__ __launch_bounds__(256)
void gemm_tf32(const float* __restrict__ A, const float* __restrict__ B,
               float* __restrict__ C, int M, int N, int K,
               const float* __restrict__ bias)
{
    extern __shared__ float gsm[];
    float* As = gsm;               // [2][128][36]
    float* Bs = gsm + 2*GSLAB;     // [2][128][36]

    const int tid  = threadIdx.x;
    const int lane = tid & 31, wid = tid >> 5;
    const int g = lane >> 2, t = lane & 3;
    const int wr = wid >> 2, wc = wid & 3;
    const int bm = blockIdx.y * 128, bn = blockIdx.x * 128;

    const int lrow = tid >> 3;            // 0..31
    const int lcol = (tid & 7) << 2;      // 0,4,...,28

    const float* Ap = A + (size_t)(bm + lrow) * K + lcol;
    const float* Bp = B + (size_t)(bn + lrow) * K + lcol;
    const size_t rstep = (size_t)32 * K;

    float4 ra[4], rb[4];
#pragma unroll
    for (int i = 0; i < 4; i++) {
        ra[i] = *(const float4*)(Ap + i * rstep);
        rb[i] = *(const float4*)(Bp + i * rstep);
    }

    float acc[4][4][4];
#pragma unroll
    for (int mf = 0; mf < 4; mf++)
#pragma unroll
        for (int nf = 0; nf < 4; nf++)
#pragma unroll
            for (int i = 0; i < 4; i++) acc[mf][nf][i] = 0.f;

    // store slab 0 into buffer 0
#pragma unroll
    for (int i = 0; i < 4; i++) {
        float* ad = &As[(lrow + i*32)*36 + lcol];
        ad[0]=tf32r(ra[i].x); ad[1]=tf32r(ra[i].y); ad[2]=tf32r(ra[i].z); ad[3]=tf32r(ra[i].w);
        float* bd = &Bs[(lrow + i*32)*36 + lcol];
        bd[0]=tf32r(rb[i].x); bd[1]=tf32r(rb[i].y); bd[2]=tf32r(rb[i].z); bd[3]=tf32r(rb[i].w);
    }
    __syncthreads();

    int p = 0;
    for (int kt = 0; kt < K; kt += 32) {
        const bool more = (kt + 32 < K);
        if (more) {
#pragma unroll
            for (int i = 0; i < 4; i++) {
                ra[i] = *(const float4*)(Ap + (kt + 32) + i * rstep);
                rb[i] = *(const float4*)(Bp + (kt + 32) + i * rstep);
            }
        }
        const float* Ab = As + p*GSLAB;
        const float* Bb = Bs + p*GSLAB;
#pragma unroll
        for (int ks = 0; ks < 4; ks++) {
            const int k0 = ks * 8;
            uint32_t af[4][4], bf[4][2];
#pragma unroll
            for (int mf = 0; mf < 4; mf++) {
                const int r = wr*64 + mf*16;
                af[mf][0] = fb(Ab[(r + g    )*36 + k0 + t    ]);
                af[mf][1] = fb(Ab[(r + g + 8)*36 + k0 + t    ]);
                af[mf][2] = fb(Ab[(r + g    )*36 + k0 + t + 4]);
                af[mf][3] = fb(Ab[(r + g + 8)*36 + k0 + t + 4]);
            }
#pragma unroll
            for (int nf = 0; nf < 4; nf++) {
                const int c = wc*32 + nf*8;
                bf[nf][0] = fb(Bb[(c + g)*36 + k0 + t    ]);
                bf[nf][1] = fb(Bb[(c + g)*36 + k0 + t + 4]);
            }
#pragma unroll
            for (int mf = 0; mf < 4; mf++)
#pragma unroll
                for (int nf = 0; nf < 4; nf++)
                    mma_tf32(acc[mf][nf], af[mf][0], af[mf][1], af[mf][2], af[mf][3],
                             bf[nf][0], bf[nf][1]);
        }
        if (more) {
            float* Aw = As + (p^1)*GSLAB;
            float* Bw = Bs + (p^1)*GSLAB;
#pragma unroll
            for (int i = 0; i < 4; i++) {
                float* ad = &Aw[(lrow + i*32)*36 + lcol];
                ad[0]=tf32r(ra[i].x); ad[1]=tf32r(ra[i].y); ad[2]=tf32r(ra[i].z); ad[3]=tf32r(ra[i].w);
                float* bd = &Bw[(lrow + i*32)*36 + lcol];
                bd[0]=tf32r(rb[i].x); bd[1]=tf32r(rb[i].y); bd[2]=tf32r(rb[i].z); bd[3]=tf32r(rb[i].w);
            }
            __syncthreads();
        }
        p ^= 1;
    }

#pragma unroll
    for (int mf = 0; mf < 4; mf++) {
        const int r = bm + wr*64 + mf*16 + g;
#pragma unroll
        for (int nf = 0; nf < 4; nf++) {
            const int c = bn + wc*32 + nf*8 + 2*t;
            float b0 = HAS_BIAS ? bias[c]     : 0.f;
            float b1 = HAS_BIAS ? bias[c + 1] : 0.f;
            *(float2*)&C[(size_t)r       * N + c] = make_float2(acc[mf][nf][0] + b0, acc[mf][nf][1] + b1);
            *(float2*)&C[(size_t)(r + 8) * N + c] = make_float2(acc[mf][nf][2] + b0, acc[mf][nf][3] + b1);
        }
    }
}

// ---------------------------------------------------------------------------
// Flash attention, tf32 tensor cores. 4 warps, BM=64 q, BN=64 keys/tile.
// P permuted C-frag -> A-frag entirely in registers (quad shfl): no Ps smem.
// smem = 53.5KB -> 4 CTAs/SM.
// ---------------------------------------------------------------------------
#define QS_STRIDE 68
#define VS_STRIDE 72
#define ATTN_SMEM_FLOATS (2*64*QS_STRIDE + 64*VS_STRIDE + 64)
#define FULLM 0xffffffffu

__global__ __launch_bounds__(128, 4)
void attn_tf32(const float* __restrict__ qkv, const int* __restrict__ mask,
               float* __restrict__ out)
{
    extern __shared__ float sm[];
    float* Qs = sm;                         // [64][68]
    float* Ks = sm + 64*QS_STRIDE;          // [64][68]
    float* Vs = sm + 2*64*QS_STRIDE;        // [64][72]
    float* maskadd = Vs + 64*VS_STRIDE;     // [64]

    const int bhead = blockIdx.y;
    const int b = bhead >> 4, h = bhead & 15;
    const int q0 = blockIdx.x * 64;
    const int tid = threadIdx.x;
    const int lane = tid & 31, wid = tid >> 5;
    const int g = lane >> 2, t = lane & 3;
    const int r0 = wid * 16;

    // shfl sources for the P C->A frag permute (within quad)
    const int srcA = (lane & ~3) | (t >> 1);
    const int srcB = srcA + 2;
    const bool odd = (t & 1);

    // ---- load Q tile (tf32-rounded) ----
    for (int i = tid; i < 64*16; i += 128) {
        const int r = i >> 4, c4 = (i & 15) << 2;
        const float* src = qkv + (size_t)(b*SEQL + q0 + r)*QKV_N + h*HDIM + c4;
        float4 v = *(const float4*)src;
        float* d = Qs + r*QS_STRIDE + c4;
        d[0]=tf32r(v.x); d[1]=tf32r(v.y); d[2]=tf32r(v.z); d[3]=tf32r(v.w);
    }

    float oc[8][4];
#pragma unroll
    for (int nf = 0; nf < 8; nf++)
#pragma unroll
        for (int i = 0; i < 4; i++) oc[nf][i] = 0.f;
    float m0 = -INFINITY, m1 = -INFINITY, l0 = 0.f, l1 = 0.f;

    for (int kt = 0; kt < SEQL; kt += 64) {
        __syncthreads();   // prior tile reads done (also covers initial Q store)
        for (int i = tid; i < 64*16; i += 128) {
            const int r = i >> 4, c4 = (i & 15) << 2;
            const size_t rowbase = (size_t)(b*SEQL + kt + r)*QKV_N + h*HDIM + c4;
            float4 kv = *(const float4*)(qkv + rowbase + EMBED);
            float* kd = Ks + r*QS_STRIDE + c4;
            kd[0]=tf32r(kv.x); kd[1]=tf32r(kv.y); kd[2]=tf32r(kv.z); kd[3]=tf32r(kv.w);
            float4 vv = *(const float4*)(qkv + rowbase + 2*EMBED);
            float* vd = Vs + r*VS_STRIDE + c4;
            vd[0]=tf32r(vv.x); vd[1]=tf32r(vv.y); vd[2]=tf32r(vv.z); vd[3]=tf32r(vv.w);
        }
        if (tid < 64)
            maskadd[tid] = (mask[b*SEQL + kt + tid] == 0) ? -INFINITY : 0.f;
        __syncthreads();

        // ---- S = Q K^T  (16 x 64 per warp) ----
        float sc[8][4];
#pragma unroll
        for (int nf = 0; nf < 8; nf++)
#pragma unroll
            for (int i = 0; i < 4; i++) sc[nf][i] = 0.f;
#pragma unroll
        for (int ks = 0; ks < 8; ks++) {
            const int k0 = ks * 8;
            const uint32_t qa0 = fb(Qs[(r0 + g    )*QS_STRIDE + k0 + t    ]);
            const uint32_t qa1 = fb(Qs[(r0 + g + 8)*QS_STRIDE + k0 + t    ]);
            const uint32_t qa2 = fb(Qs[(r0 + g    )*QS_STRIDE + k0 + t + 4]);
            const uint32_t qa3 = fb(Qs[(r0 + g + 8)*QS_STRIDE + k0 + t + 4]);
#pragma unroll
            for (int nf = 0; nf < 8; nf++) {
                uint32_t kb0 = fb(Ks[(nf*8 + g)*QS_STRIDE + k0 + t    ]);
                uint32_t kb1 = fb(Ks[(nf*8 + g)*QS_STRIDE + k0 + t + 4]);
                mma_tf32(sc[nf], qa0, qa1, qa2, qa3, kb0, kb1);
            }
        }

        // ---- scale + mask + row max ----
        float mx0 = -INFINITY, mx1 = -INFINITY;
#pragma unroll
        for (int nf = 0; nf < 8; nf++) {
            const float ma = maskadd[nf*8 + 2*t];
            const float mb = maskadd[nf*8 + 2*t + 1];
            sc[nf][0] = sc[nf][0]*0.125f + ma;
            sc[nf][1] = sc[nf][1]*0.125f + mb;
            sc[nf][2] = sc[nf][2]*0.125f + ma;
            sc[nf][3] = sc[nf][3]*0.125f + mb;
            mx0 = fmaxf(mx0, fmaxf(sc[nf][0], sc[nf][1]));
            mx1 = fmaxf(mx1, fmaxf(sc[nf][2], sc[nf][3]));
        }
        mx0 = fmaxf(mx0, __shfl_xor_sync(FULLM, mx0, 1));
        mx0 = fmaxf(mx0, __shfl_xor_sync(FULLM, mx0, 2));
        mx1 = fmaxf(mx1, __shfl_xor_sync(FULLM, mx1, 1));
        mx1 = fmaxf(mx1, __shfl_xor_sync(FULLM, mx1, 2));

        const float nm0 = fmaxf(m0, mx0), nm1 = fmaxf(m1, mx1);
        const float gd0 = (nm0 == -INFINITY) ? 0.f : nm0;
        const float gd1 = (nm1 == -INFINITY) ? 0.f : nm1;
        const float alpha0 = __expf(m0 - gd0);
        const float alpha1 = __expf(m1 - gd1);

        // ---- exp + in-register C->A fragment permute of P ----
        uint32_t pa[8][4];
        float rs0 = 0.f, rs1 = 0.f;
#pragma unroll
        for (int nf = 0; nf < 8; nf++) {
            const float p0 = __expf(sc[nf][0] - gd0);
            const float p1 = __expf(sc[nf][1] - gd0);
            const float p2 = __expf(sc[nf][2] - gd1);
            const float p3 = __expf(sc[nf][3] - gd1);
            rs0 += p0 + p1;  rs1 += p2 + p3;
            const uint32_t u0 = fb(tf32r(p0)), u1 = fb(tf32r(p1));
            const uint32_t u2 = fb(tf32r(p2)), u3 = fb(tf32r(p3));
            // row g, cols t and t+4
            const uint32_t s0A = __shfl_sync(FULLM, u0, srcA);
            const uint32_t s1A = __shfl_sync(FULLM, u1, srcA);
            const uint32_t s0B = __shfl_sync(FULLM, u0, srcB);
            const uint32_t s1B = __shfl_sync(FULLM, u1, srcB);
            pa[nf][0] = odd ? s1A : s0A;
            pa[nf][2] = odd ? s1B : s0B;
            // row g+8, cols t and t+4
            const uint32_t s2A = __shfl_sync(FULLM, u2, srcA);
            const uint32_t s3A = __shfl_sync(FULLM, u3, srcA);
            const uint32_t s2B = __shfl_sync(FULLM, u2, srcB);
            const uint32_t s3B = __shfl_sync(FULLM, u3, srcB);
            pa[nf][1] = odd ? s3A : s2A;
            pa[nf][3] = odd ? s3B : s2B;
        }
        rs0 += __shfl_xor_sync(FULLM, rs0, 1);
        rs0 += __shfl_xor_sync(FULLM, rs0, 2);
        rs1 += __shfl_xor_sync(FULLM, rs1, 1);
        rs1 += __shfl_xor_sync(FULLM, rs1, 2);

        l0 = l0*alpha0 + rs0;  l1 = l1*alpha1 + rs1;
        m0 = nm0;  m1 = nm1;
#pragma unroll
        for (int nf = 0; nf < 8; nf++) {
            oc[nf][0] *= alpha0; oc[nf][1] *= alpha0;
            oc[nf][2] *= alpha1; oc[nf][3] *= alpha1;
        }

        // ---- O += P V ----
#pragma unroll
        for (int ks = 0; ks < 8; ks++) {
            const int k0 = ks * 8;
#pragma unroll
            for (int nf = 0; nf < 8; nf++) {
                uint32_t vb0 = fb(Vs[(k0 + t    )*VS_STRIDE + nf*8 + g]);
                uint32_t vb1 = fb(Vs[(k0 + t + 4)*VS_STRIDE + nf*8 + g]);
                mma_tf32(oc[nf], pa[ks][0], pa[ks][1], pa[ks][2], pa[ks][3], vb0, vb1);
            }
        }
    }

    // ---- normalize + write ----
    const float inv0 = 1.f / l0, inv1 = 1.f / l1;
    const int row = b*SEQL + q0 + r0 + g;
#pragma unroll
    for (int nf = 0; nf < 8; nf++) {
        const int c = h*HDIM + nf*8 + 2*t;
        *(float2*)&out[(size_t)row       * EMBED + c] = make_float2(oc[nf][0]*inv0, oc[nf][1]*inv0);
        *(float2*)&out[(size_t)(row + 8) * EMBED + c] = make_float2(oc[nf][2]*inv1, oc[nf][3]*inv1);
    }
}

// ---------------------------------------------------------------------------
extern "C" void kernel_launch(void* const* d_in, const int* in_sizes, int n_in,
                              void* d_out, int out_size)
{
    const float* x     = (const float*)d_in[0];
    const int*   mask  = (const int*)  d_in[1];
    const float* qkv_w = (const float*)d_in[2];
    const float* out_w = (const float*)d_in[3];
    const float* out_b = (const float*)d_in[4];
    float* out = (float*)d_out;

    float* qkv;  cudaGetSymbolAddress((void**)&qkv,  g_qkv);
    float* attn; cudaGetSymbolAddress((void**)&attn, g_attn);

    const int attn_smem = ATTN_SMEM_FLOATS * (int)sizeof(float);
    cudaFuncSetAttribute(attn_tf32, cudaFuncAttributeMaxDynamicSharedMemorySize, attn_smem);
    cudaFuncSetAttribute(gemm_tf32<false>, cudaFuncAttributeMaxDynamicSharedMemorySize, GEMM_SMEM_BYTES);
    cudaFuncSetAttribute(gemm_tf32<true>,  cudaFuncAttributeMaxDynamicSharedMemorySize, GEMM_SMEM_BYTES);

    // 1) QKV projection
    gemm_tf32<false><<<dim3(QKV_N/128, M_TOTAL/128), 256, GEMM_SMEM_BYTES>>>(
        x, qkv_w, qkv, M_TOTAL, QKV_N, EMBED, nullptr);

    // 2) Attention
    attn_tf32<<<dim3(SEQL/64, BATCH*HEADS), 128, attn_smem>>>(qkv, mask, attn);

    // 3) Output projection
    gemm_tf32<true><<<dim3(EMBED/128, M_TOTAL/128), 256, GEMM_SMEM_BYTES>>>(
        attn, out_w, out, M_TOTAL, EMBED, EMBED, out_b);
}

// round 11
// speedup vs baseline: 6.4631x; 1.7172x over previous
#include <cuda_runtime.h>
#include <cuda_fp16.h>
#include <math.h>
#include <stdint.h>

#define BATCH   2
#define SEQL    2048
#define EMBED   1024
#define HEADS   16
#define HDIM    64
#define M_TOTAL (BATCH*SEQL)   /* 4096 */
#define QKV_N   (3*EMBED)      /* 3072 */

// Scratch (alloc-free rule: __device__ globals)
__device__ __half g_qkv [M_TOTAL * (size_t)QKV_N];   // half: written by gemm<half>
__device__ float  g_attn[M_TOTAL * (size_t)EMBED];

// ---------------------------------------------------------------------------
__device__ __forceinline__ uint32_t h2b(__half2 h) { return *(uint32_t*)&h; }

// D(16x8) += A(16x16) * B(16x8), fp16 operands, fp32 accum. row.col.
__device__ __forceinline__ void mma_f16(float c[4],
    uint32_t a0, uint32_t a1, uint32_t a2, uint32_t a3,
    uint32_t b0, uint32_t b1)
{
    asm volatile(
        "mma.sync.aligned.m16n8k16.row.col.f32.f16.f16.f32 "
        "{%0,%1,%2,%3}, {%4,%5,%6,%7}, {%8,%9}, {%0,%1,%2,%3};"
        : "+f"(c[0]), "+f"(c[1]), "+f"(c[2]), "+f"(c[3])
        : "r"(a0), "r"(a1), "r"(a2), "r"(a3), "r"(b0), "r"(b1));
}

__device__ __forceinline__ void ldsm_x4_t(uint32_t& v0, uint32_t& v1,
                                          uint32_t& v2, uint32_t& v3,
                                          const void* p)
{
    uint32_t a = (uint32_t)__cvta_generic_to_shared(p);
    asm volatile("ldmatrix.sync.aligned.m8n8.x4.trans.shared.b16 {%0,%1,%2,%3}, [%4];"
                 : "=r"(v0), "=r"(v1), "=r"(v2), "=r"(v3) : "r"(a));
}

// ---------------------------------------------------------------------------
// C[M,N] = A[M,K] @ B[N,K]^T (+bias), fp16 tensor cores, fp32 accum.
// 128x128 block tile, BK=32, 8 warps (2x4), warp tile 64x32.
// TC = __half (no bias) or float (+bias).
// ---------------------------------------------------------------------------
#define GST 40   /* smem row stride in halves: 20g+t bank-bijective */

template<typename TC, bool HAS_BIAS>
__global__ __launch_bounds__(256)
void gemm_f16(const float* __restrict__ A, const float* __restrict__ B,
              TC* __restrict__ C, int M, int N, int K,
              const float* __restrict__ bias)
{
    __shared__ __half As[2][128][GST];
    __shared__ __half Bs[2][128][GST];

    const int tid  = threadIdx.x;
    const int lane = tid & 31, wid = tid >> 5;
    const int g = lane >> 2, t = lane & 3;
    const int wr = wid >> 2, wc = wid & 3;
    const int bm = blockIdx.y * 128, bn = blockIdx.x * 128;

    const int lrow = tid >> 3;            // 0..31
    const int lcol = (tid & 7) << 2;      // 0,4,...,28

    const float* Ap = A + (size_t)(bm + lrow) * K + lcol;
    const float* Bp = B + (size_t)(bn + lrow) * K + lcol;
    const size_t rstep = (size_t)32 * K;

    float4 ra[4], rb[4];
#pragma unroll
    for (int i = 0; i < 4; i++) {
        ra[i] = *(const float4*)(Ap + i * rstep);
        rb[i] = *(const float4*)(Bp + i * rstep);
    }

    float acc[4][4][4];
#pragma unroll
    for (int mf = 0; mf < 4; mf++)
#pragma unroll
        for (int nf = 0; nf < 4; nf++)
#pragma unroll
            for (int i = 0; i < 4; i++) acc[mf][nf][i] = 0.f;

#pragma unroll
    for (int i = 0; i < 4; i++) {
        *(__half2*)&As[0][lrow + i*32][lcol]     = __floats2half2_rn(ra[i].x, ra[i].y);
        *(__half2*)&As[0][lrow + i*32][lcol + 2] = __floats2half2_rn(ra[i].z, ra[i].w);
        *(__half2*)&Bs[0][lrow + i*32][lcol]     = __floats2half2_rn(rb[i].x, rb[i].y);
        *(__half2*)&Bs[0][lrow + i*32][lcol + 2] = __floats2half2_rn(rb[i].z, rb[i].w);
    }
    __syncthreads();

    int p = 0;
    for (int kt = 0; kt < K; kt += 32) {
        const bool more = (kt + 32 < K);
        if (more) {
#pragma unroll
            for (int i = 0; i < 4; i++) {
                ra[i] = *(const float4*)(Ap + (kt + 32) + i * rstep);
                rb[i] = *(const float4*)(Bp + (kt + 32) + i * rstep);
            }
        }
#pragma unroll
        for (int ks = 0; ks < 2; ks++) {            // k16 steps in BK=32
            const int k0 = ks * 16;
            uint32_t af[4][4], bf[4][2];
#pragma unroll
            for (int mf = 0; mf < 4; mf++) {
                const int r = wr*64 + mf*16;
                af[mf][0] = *(const uint32_t*)&As[p][r + g    ][k0 + 2*t    ];
                af[mf][1] = *(const uint32_t*)&As[p][r + g + 8][k0 + 2*t    ];
                af[mf][2] = *(const uint32_t*)&As[p][r + g    ][k0 + 2*t + 8];
                af[mf][3] = *(const uint32_t*)&As[p][r + g + 8][k0 + 2*t + 8];
            }
#pragma unroll
            for (int nf = 0; nf < 4; nf++) {
                const int c = wc*32 + nf*8;
                bf[nf][0] = *(const uint32_t*)&Bs[p][c + g][k0 + 2*t    ];
                bf[nf][1] = *(const uint32_t*)&Bs[p][c + g][k0 + 2*t + 8];
            }
#pragma unroll
            for (int mf = 0; mf < 4; mf++)
#pragma unroll
                for (int nf = 0; nf < 4; nf++)
                    mma_f16(acc[mf][nf], af[mf][0], af[mf][1], af[mf][2], af[mf][3],
                            bf[nf][0], bf[nf][1]);
        }
        if (more) {
            const int q = p ^ 1;
#pragma unroll
            for (int i = 0; i < 4; i++) {
                *(__half2*)&As[q][lrow + i*32][lcol]     = __floats2half2_rn(ra[i].x, ra[i].y);
                *(__half2*)&As[q][lrow + i*32][lcol + 2] = __floats2half2_rn(ra[i].z, ra[i].w);
                *(__half2*)&Bs[q][lrow + i*32][lcol]     = __floats2half2_rn(rb[i].x, rb[i].y);
                *(__half2*)&Bs[q][lrow + i*32][lcol + 2] = __floats2half2_rn(rb[i].z, rb[i].w);
            }
            __syncthreads();
        }
        p ^= 1;
    }

#pragma unroll
    for (int mf = 0; mf < 4; mf++) {
        const int r = bm + wr*64 + mf*16 + g;
#pragma unroll
        for (int nf = 0; nf < 4; nf++) {
            const int c = bn + wc*32 + nf*8 + 2*t;
            if constexpr (sizeof(TC) == 2) {
                *(__half2*)&C[(size_t)r       * N + c] = __floats2half2_rn(acc[mf][nf][0], acc[mf][nf][1]);
                *(__half2*)&C[(size_t)(r + 8) * N + c] = __floats2half2_rn(acc[mf][nf][2], acc[mf][nf][3]);
            } else {
                float b0 = HAS_BIAS ? bias[c]     : 0.f;
                float b1 = HAS_BIAS ? bias[c + 1] : 0.f;
                *(float2*)&C[(size_t)r       * N + c] = make_float2(acc[mf][nf][0] + b0, acc[mf][nf][1] + b1);
                *(float2*)&C[(size_t)(r + 8) * N + c] = make_float2(acc[mf][nf][2] + b0, acc[mf][nf][3] + b1);
            }
        }
    }
}

// ---------------------------------------------------------------------------
// Flash attention, fp16 tensor cores (m16n8k16), fp32 softmax/accum.
// 4 warps, BM=64 q, BN=64 keys/tile. P: C-frag -> A-frag by half2 packing (free).
// V B-frags via ldmatrix.x4.trans on natural [key][d] layout.
// ---------------------------------------------------------------------------
#define AST 72   /* smem row stride in halves: word = 36r -> 4g+t bank-bijective */
#define FULLM 0xffffffffu

__global__ __launch_bounds__(128, 4)
void attn_f16(const __half* __restrict__ qkv, const int* __restrict__ mask,
              float* __restrict__ out)
{
    __shared__ __half Qh[64][AST];
    __shared__ __half Kh[64][AST];
    __shared__ __half Vh[64][AST];
    __shared__ float  maskadd[64];

    const int bhead = blockIdx.y;
    const int b = bhead >> 4, h = bhead & 15;
    const int q0 = blockIdx.x * 64;
    const int tid = threadIdx.x;
    const int lane = tid & 31, wid = tid >> 5;
    const int g = lane >> 2, t = lane & 3;
    const int r0 = wid * 16;

    // ldmatrix lane addressing: matrix m = lane>>3, row-in-matrix = lane&7
    const int lm_m = lane >> 3, lm_r = lane & 7;

    // ---- load Q tile (already half) ----
    for (int i = tid; i < 64*16; i += 128) {
        const int r = i >> 4, c4 = (i & 15) << 2;
        *(uint2*)&Qh[r][c4] =
            *(const uint2*)(qkv + (size_t)(b*SEQL + q0 + r)*QKV_N + h*HDIM + c4);
    }

    float oc[8][4];
#pragma unroll
    for (int nf = 0; nf < 8; nf++)
#pragma unroll
        for (int i = 0; i < 4; i++) oc[nf][i] = 0.f;
    float m0 = -INFINITY, m1 = -INFINITY, l0 = 0.f, l1 = 0.f;

    for (int kt = 0; kt < SEQL; kt += 64) {
        __syncthreads();
        for (int i = tid; i < 64*16; i += 128) {
            const int r = i >> 4, c4 = (i & 15) << 2;
            const size_t rowbase = (size_t)(b*SEQL + kt + r)*QKV_N + h*HDIM + c4;
            *(uint2*)&Kh[r][c4] = *(const uint2*)(qkv + rowbase + EMBED);
            *(uint2*)&Vh[r][c4] = *(const uint2*)(qkv + rowbase + 2*EMBED);
        }
        if (tid < 64)
            maskadd[tid] = (mask[b*SEQL + kt + tid] == 0) ? -INFINITY : 0.f;
        __syncthreads();

        // ---- S = Q K^T  (16 x 64 per warp), 4 k16 steps ----
        float sc[8][4];
#pragma unroll
        for (int nf = 0; nf < 8; nf++)
#pragma unroll
            for (int i = 0; i < 4; i++) sc[nf][i] = 0.f;
#pragma unroll
        for (int ks = 0; ks < 4; ks++) {
            const int k0 = ks * 16;
            const uint32_t qa0 = *(const uint32_t*)&Qh[r0 + g    ][k0 + 2*t    ];
            const uint32_t qa1 = *(const uint32_t*)&Qh[r0 + g + 8][k0 + 2*t    ];
            const uint32_t qa2 = *(const uint32_t*)&Qh[r0 + g    ][k0 + 2*t + 8];
            const uint32_t qa3 = *(const uint32_t*)&Qh[r0 + g + 8][k0 + 2*t + 8];
#pragma unroll
            for (int nf = 0; nf < 8; nf++) {
                uint32_t kb0 = *(const uint32_t*)&Kh[nf*8 + g][k0 + 2*t    ];
                uint32_t kb1 = *(const uint32_t*)&Kh[nf*8 + g][k0 + 2*t + 8];
                mma_f16(sc[nf], qa0, qa1, qa2, qa3, kb0, kb1);
            }
        }

        // ---- scale + mask + row max ----
        float mx0 = -INFINITY, mx1 = -INFINITY;
#pragma unroll
        for (int nf = 0; nf < 8; nf++) {
            const float ma = maskadd[nf*8 + 2*t];
            const float mb = maskadd[nf*8 + 2*t + 1];
            sc[nf][0] = sc[nf][0]*0.125f + ma;
            sc[nf][1] = sc[nf][1]*0.125f + mb;
            sc[nf][2] = sc[nf][2]*0.125f + ma;
            sc[nf][3] = sc[nf][3]*0.125f + mb;
            mx0 = fmaxf(mx0, fmaxf(sc[nf][0], sc[nf][1]));
            mx1 = fmaxf(mx1, fmaxf(sc[nf][2], sc[nf][3]));
        }
        mx0 = fmaxf(mx0, __shfl_xor_sync(FULLM, mx0, 1));
        mx0 = fmaxf(mx0, __shfl_xor_sync(FULLM, mx0, 2));
        mx1 = fmaxf(mx1, __shfl_xor_sync(FULLM, mx1, 1));
        mx1 = fmaxf(mx1, __shfl_xor_sync(FULLM, mx1, 2));

        const float nm0 = fmaxf(m0, mx0), nm1 = fmaxf(m1, mx1);
        const float gd0 = (nm0 == -INFINITY) ? 0.f : nm0;
        const float gd1 = (nm1 == -INFINITY) ? 0.f : nm1;
        const float alpha0 = __expf(m0 - gd0);
        const float alpha1 = __expf(m1 - gd1);

        // ---- exp (fp32) ----
        float rs0 = 0.f, rs1 = 0.f;
#pragma unroll
        for (int nf = 0; nf < 8; nf++) {
            sc[nf][0] = __expf(sc[nf][0] - gd0);
            sc[nf][1] = __expf(sc[nf][1] - gd0);
            sc[nf][2] = __expf(sc[nf][2] - gd1);
            sc[nf][3] = __expf(sc[nf][3] - gd1);
            rs0 += sc[nf][0] + sc[nf][1];
            rs1 += sc[nf][2] + sc[nf][3];
        }
        rs0 += __shfl_xor_sync(FULLM, rs0, 1);
        rs0 += __shfl_xor_sync(FULLM, rs0, 2);
        rs1 += __shfl_xor_sync(FULLM, rs1, 1);
        rs1 += __shfl_xor_sync(FULLM, rs1, 2);

        l0 = l0*alpha0 + rs0;  l1 = l1*alpha1 + rs1;
        m0 = nm0;  m1 = nm1;
#pragma unroll
        for (int nf = 0; nf < 8; nf++) {
            oc[nf][0] *= alpha0; oc[nf][1] *= alpha0;
            oc[nf][2] *= alpha1; oc[nf][3] *= alpha1;
        }

        // ---- P A-frags: pack C-frag pairs to half2 (layout-exact, no shfl) ----
        uint32_t pa[4][4];
#pragma unroll
        for (int ks = 0; ks < 4; ks++) {
            pa[ks][0] = h2b(__floats2half2_rn(sc[2*ks    ][0], sc[2*ks    ][1]));
            pa[ks][1] = h2b(__floats2half2_rn(sc[2*ks    ][2], sc[2*ks    ][3]));
            pa[ks][2] = h2b(__floats2half2_rn(sc[2*ks + 1][0], sc[2*ks + 1][1]));
            pa[ks][3] = h2b(__floats2half2_rn(sc[2*ks + 1][2], sc[2*ks + 1][3]));
        }

        // ---- O += P V : V B-frags via ldmatrix.x4.trans on natural layout ----
#pragma unroll
        for (int ks = 0; ks < 4; ks++) {
#pragma unroll
            for (int nfp = 0; nfp < 4; nfp++) {
                const int row = 16*ks + 8*(lm_m & 1) + lm_r;
                const int col = 8*(2*nfp + (lm_m >> 1));
                uint32_t v0, v1, v2, v3;
                ldsm_x4_t(v0, v1, v2, v3, &Vh[row][col]);
                mma_f16(oc[2*nfp    ], pa[ks][0], pa[ks][1], pa[ks][2], pa[ks][3], v0, v1);
                mma_f16(oc[2*nfp + 1], pa[ks][0], pa[ks][1], pa[ks][2], pa[ks][3], v2, v3);
            }
        }
    }

    // ---- normalize + write (fp32) ----
    const float inv0 = 1.f / l0, inv1 = 1.f / l1;
    const int row = b*SEQL + q0 + r0 + g;
#pragma unroll
    for (int nf = 0; nf < 8; nf++) {
        const int c = h*HDIM + nf*8 + 2*t;
        *(float2*)&out[(size_t)row       * EMBED + c] = make_float2(oc[nf][0]*inv0, oc[nf][1]*inv0);
        *(float2*)&out[(size_t)(row + 8) * EMBED + c] = make_float2(oc[nf][2]*inv1, oc[nf][3]*inv1);
    }
}

// ---------------------------------------------------------------------------
extern "C" void kernel_launch(void* const* d_in, const int* in_sizes, int n_in,
                              void* d_out, int out_size)
{
    const float* x     = (const float*)d_in[0];
    const int*   mask  = (const int*)  d_in[1];
    const float* qkv_w = (const float*)d_in[2];
    const float* out_w = (const float*)d_in[3];
    const float* out_b = (const float*)d_in[4];
    float* out = (float*)d_out;

    __half* qkv; cudaGetSymbolAddress((void**)&qkv,  g_qkv);
    float* attn; cudaGetSymbolAddress((void**)&attn, g_attn);

    // 1) QKV projection -> half
    gemm_f16<__half, false><<<dim3(QKV_N/128, M_TOTAL/128), 256>>>(
        x, qkv_w, qkv, M_TOTAL, QKV_N, EMBED, nullptr);

    // 2) Attention
    attn_f16<<<dim3(SEQL/64, BATCH*HEADS), 128>>>(qkv, mask, attn);

    // 3) Output projection (+bias) -> float
    gemm_f16<float, true><<<dim3(EMBED/128, M_TOTAL/128), 256>>>(
        attn, out_w, out, M_TOTAL, EMBED, EMBED, out_b);
}